// round 3
// baseline (speedup 1.0000x reference)
#include <cuda_runtime.h>

#define NTOK 8192
#define DIM  256
#define BM   64
#define BK   64

// Scratch for Q, K, V projections (8 MB each) — __device__ globals, no allocs.
__device__ float g_Q[NTOK * DIM];
__device__ float g_K[NTOK * DIM];
__device__ float g_V[NTOK * DIM];

// ---------------------------------------------------------------------------
// Projection GEMM: O = X @ W  for W in {WQ, WK, WV}
// grid = (8192/64, 12): blockIdx.y selects weight (y/4) and 64-col tile (y%4)
// 64x64 block tile, 256 threads, 4x4 micro-tile, K-step 32.
// ---------------------------------------------------------------------------
__global__ __launch_bounds__(256) void proj_kernel(
    const float* __restrict__ X,
    const float* __restrict__ WQ,
    const float* __restrict__ WK,
    const float* __restrict__ WV)
{
    __shared__ float As[64][36];   // pad 36 keeps float4 stores aligned, spreads banks
    __shared__ float Bs[32][64];

    const int tid  = threadIdx.x;
    const int tx   = tid & 15;
    const int ty   = tid >> 4;
    const int row0 = blockIdx.x * 64;
    const int wsel = blockIdx.y >> 2;
    const int colB = (blockIdx.y & 3) * 64;

    const float* __restrict__ W = (wsel == 0) ? WQ : (wsel == 1) ? WK : WV;
    float* __restrict__ O       = (wsel == 0) ? g_Q : (wsel == 1) ? g_K : g_V;

    float acc[4][4] = {};

    for (int k0 = 0; k0 < DIM; k0 += 32) {
        // load A tile 64x32 (float4 along k)
        #pragma unroll
        for (int it = 0; it < 2; ++it) {
            int s  = tid + it * 256;          // 512 float4 slots
            int r  = s >> 3;
            int k4 = (s & 7) * 4;
            float4 v = *reinterpret_cast<const float4*>(X + (row0 + r) * DIM + k0 + k4);
            *reinterpret_cast<float4*>(&As[r][k4]) = v;
        }
        // load B tile 32x64 (float4 along cols)
        #pragma unroll
        for (int it = 0; it < 2; ++it) {
            int s  = tid + it * 256;          // 512 float4 slots
            int kk = s >> 4;
            int c4 = (s & 15) * 4;
            float4 v = *reinterpret_cast<const float4*>(W + (k0 + kk) * DIM + colB + c4);
            *reinterpret_cast<float4*>(&Bs[kk][c4]) = v;
        }
        __syncthreads();

        #pragma unroll 8
        for (int kk = 0; kk < 32; ++kk) {
            float4 b = *reinterpret_cast<const float4*>(&Bs[kk][tx * 4]);
            float a0 = As[ty * 4 + 0][kk];
            float a1 = As[ty * 4 + 1][kk];
            float a2 = As[ty * 4 + 2][kk];
            float a3 = As[ty * 4 + 3][kk];
            acc[0][0] += a0 * b.x; acc[0][1] += a0 * b.y; acc[0][2] += a0 * b.z; acc[0][3] += a0 * b.w;
            acc[1][0] += a1 * b.x; acc[1][1] += a1 * b.y; acc[1][2] += a1 * b.z; acc[1][3] += a1 * b.w;
            acc[2][0] += a2 * b.x; acc[2][1] += a2 * b.y; acc[2][2] += a2 * b.z; acc[2][3] += a2 * b.w;
            acc[3][0] += a3 * b.x; acc[3][1] += a3 * b.y; acc[3][2] += a3 * b.z; acc[3][3] += a3 * b.w;
        }
        __syncthreads();
    }

    #pragma unroll
    for (int i = 0; i < 4; ++i) {
        float4 v = make_float4(acc[i][0], acc[i][1], acc[i][2], acc[i][3]);
        *reinterpret_cast<float4*>(O + (row0 + ty * 4 + i) * DIM + colB + tx * 4) = v;
    }
}

// ---------------------------------------------------------------------------
// Flash attention: out = softmax(Q K^T) V, fp32, no scaling.
// 128 CTAs (BM=64 queries each), 256 threads = 8 warps.
// Warp ry owns S/O rows [8*ry, 8*ry+8); lane cx owns S cols {2cx,2cx+1},
// O cols [8*cx, 8*cx+8). Row softmax reductions are whole-warp shuffles.
// ---------------------------------------------------------------------------
__device__ __forceinline__ float warp_max(float v) {
    #pragma unroll
    for (int o = 16; o > 0; o >>= 1) v = fmaxf(v, __shfl_xor_sync(0xffffffffu, v, o));
    return v;
}
__device__ __forceinline__ float warp_sum(float v) {
    #pragma unroll
    for (int o = 16; o > 0; o >>= 1) v += __shfl_xor_sync(0xffffffffu, v, o);
    return v;
}

extern __shared__ float fa_smem[];

__global__ __launch_bounds__(256, 1) void flash_kernel(float* __restrict__ out)
{
    float* QsT = fa_smem;                 // [256][64]  Q^T  (64 KB)
    float* KsT = QsT + DIM * BM;          // [256][64]  K^T  (64 KB)
    float* Vs  = KsT + DIM * BK;          // [64][256]  V    (64 KB)
    float* Ps  = Vs + BK * DIM;           // [64][64]   P    (16 KB)

    const int tid = threadIdx.x;
    const int ry  = tid >> 5;             // warp id 0..7
    const int cx  = tid & 31;             // lane
    const int q0  = blockIdx.x * BM;

    // Load Q tile transposed: QsT[k][r] = Q[q0+r][k]
    for (int s = tid; s < 64 * 64; s += 256) {   // 4096 float4 slots
        int k4 = s >> 6;
        int r  = s & 63;
        float4 v = *reinterpret_cast<const float4*>(g_Q + (q0 + r) * DIM + k4 * 4);
        QsT[(k4 * 4 + 0) * BM + r] = v.x;
        QsT[(k4 * 4 + 1) * BM + r] = v.y;
        QsT[(k4 * 4 + 2) * BM + r] = v.z;
        QsT[(k4 * 4 + 3) * BM + r] = v.w;
    }

    float acc[8][8];
    float mrow[8], lrow[8];
    #pragma unroll
    for (int i = 0; i < 8; ++i) {
        mrow[i] = -3.402823466e38f;
        lrow[i] = 0.0f;
        #pragma unroll
        for (int j = 0; j < 8; ++j) acc[i][j] = 0.0f;
    }

    for (int t = 0; t < NTOK / BK; ++t) {
        const int k0 = t * BK;
        __syncthreads();   // previous-iter reads of KsT/Vs done (also covers Q load at t=0)

        // Load K tile transposed
        for (int s = tid; s < 64 * 64; s += 256) {
            int k4 = s >> 6;
            int r  = s & 63;
            float4 v = *reinterpret_cast<const float4*>(g_K + (k0 + r) * DIM + k4 * 4);
            KsT[(k4 * 4 + 0) * BK + r] = v.x;
            KsT[(k4 * 4 + 1) * BK + r] = v.y;
            KsT[(k4 * 4 + 2) * BK + r] = v.z;
            KsT[(k4 * 4 + 3) * BK + r] = v.w;
        }
        // Load V tile row-major
        for (int s = tid; s < 64 * 64; s += 256) {
            int r  = s >> 6;
            int c4 = s & 63;
            float4 v = *reinterpret_cast<const float4*>(g_V + (k0 + r) * DIM + c4 * 4);
            *reinterpret_cast<float4*>(Vs + r * DIM + c4 * 4) = v;
        }
        __syncthreads();

        // ---- S = Q K^T : each thread 8 rows x 2 cols over K-dim 256 ----
        float sv[8][2];
        #pragma unroll
        for (int i = 0; i < 8; ++i) { sv[i][0] = 0.0f; sv[i][1] = 0.0f; }

        #pragma unroll 4
        for (int kk = 0; kk < DIM; ++kk) {
            const float4 qa = *reinterpret_cast<const float4*>(QsT + kk * BM + 8 * ry);
            const float4 qb = *reinterpret_cast<const float4*>(QsT + kk * BM + 8 * ry + 4);
            const float2 kf = *reinterpret_cast<const float2*>(KsT + kk * BK + 2 * cx);
            sv[0][0] += qa.x * kf.x; sv[0][1] += qa.x * kf.y;
            sv[1][0] += qa.y * kf.x; sv[1][1] += qa.y * kf.y;
            sv[2][0] += qa.z * kf.x; sv[2][1] += qa.z * kf.y;
            sv[3][0] += qa.w * kf.x; sv[3][1] += qa.w * kf.y;
            sv[4][0] += qb.x * kf.x; sv[4][1] += qb.x * kf.y;
            sv[5][0] += qb.y * kf.x; sv[5][1] += qb.y * kf.y;
            sv[6][0] += qb.z * kf.x; sv[6][1] += qb.z * kf.y;
            sv[7][0] += qb.w * kf.x; sv[7][1] += qb.w * kf.y;
        }

        // ---- online softmax (per-row, whole-warp reductions) ----
        #pragma unroll
        for (int i = 0; i < 8; ++i) {
            float mx = warp_max(fmaxf(sv[i][0], sv[i][1]));
            float mnew  = fmaxf(mrow[i], mx);
            float scale = __expf(mrow[i] - mnew);
            mrow[i] = mnew;
            float p0 = __expf(sv[i][0] - mnew);
            float p1 = __expf(sv[i][1] - mnew);
            float rs = warp_sum(p0 + p1);
            lrow[i] = lrow[i] * scale + rs;
            #pragma unroll
            for (int j = 0; j < 8; ++j) acc[i][j] *= scale;
            *reinterpret_cast<float2*>(Ps + (8 * ry + i) * BK + 2 * cx) = make_float2(p0, p1);
        }
        __syncwarp();   // Ps rows are warp-private: warp sync suffices

        // ---- O += P V : each thread 8 rows x 8 cols over 64 keys ----
        for (int kj = 0; kj < BK; ++kj) {
            const float4 va = *reinterpret_cast<const float4*>(Vs + kj * DIM + 8 * cx);
            const float4 vb = *reinterpret_cast<const float4*>(Vs + kj * DIM + 8 * cx + 4);
            #pragma unroll
            for (int i = 0; i < 8; ++i) {
                const float p = Ps[(8 * ry + i) * BK + kj];
                acc[i][0] += p * va.x;
                acc[i][1] += p * va.y;
                acc[i][2] += p * va.z;
                acc[i][3] += p * va.w;
                acc[i][4] += p * vb.x;
                acc[i][5] += p * vb.y;
                acc[i][6] += p * vb.z;
                acc[i][7] += p * vb.w;
            }
        }
    }

    // ---- epilogue: normalize and store ----
    #pragma unroll
    for (int i = 0; i < 8; ++i) {
        const float inv = 1.0f / lrow[i];
        float4 a = make_float4(acc[i][0] * inv, acc[i][1] * inv, acc[i][2] * inv, acc[i][3] * inv);
        float4 b = make_float4(acc[i][4] * inv, acc[i][5] * inv, acc[i][6] * inv, acc[i][7] * inv);
        float* dst = out + (q0 + 8 * ry + i) * DIM + 8 * cx;
        *reinterpret_cast<float4*>(dst)     = a;
        *reinterpret_cast<float4*>(dst + 4) = b;
    }
}

// ---------------------------------------------------------------------------

static const int FA_SMEM_BYTES = (3 * DIM * BM + BK * BK) * (int)sizeof(float); // 212992

extern "C" void kernel_launch(void* const* d_in, const int* in_sizes, int n_in,
                              void* d_out, int out_size)
{
    (void)in_sizes; (void)n_in; (void)out_size;
    const float* X  = (const float*)d_in[0];
    const float* WQ = (const float*)d_in[1];
    const float* WK = (const float*)d_in[2];
    const float* WV = (const float*)d_in[3];
    float* out = (float*)d_out;

    cudaFuncSetAttribute(flash_kernel, cudaFuncAttributeMaxDynamicSharedMemorySize, FA_SMEM_BYTES);

    proj_kernel<<<dim3(NTOK / 64, 12), 256>>>(X, WQ, WK, WV);
    flash_kernel<<<NTOK / BM, 256, FA_SMEM_BYTES>>>(out);
}

// round 7
// speedup vs baseline: 2.3126x; 2.3126x over previous
#include <cuda_runtime.h>
#include <cstdint>

#define NTOK 8192
#define DIM  256
#define BM   64
#define BK   32
#define NT   (NTOK / BK)     // 256 key tiles

#define LDQ  260             // 256 + 4 pad (floats)
#define LDK  260
#define LDV  36              // 32 + 4 pad
#define LDP  36

// Scratch: Q, K row-major; V stored TRANSPOSED [dim][ntok].
__device__ float g_Q[NTOK * DIM];
__device__ float g_K[NTOK * DIM];
__device__ float g_VT[DIM * NTOK];

// round to tf32 (RNA) — returns fp32 value with low 13 mantissa bits zeroed,
// rounded to nearest. cvt.rna.tf32.f32 destination is a .b32 register.
__device__ __forceinline__ float tf32_rna(float x) {
    uint32_t r;
    asm("cvt.rna.tf32.f32 %0, %1;" : "=r"(r) : "f"(x));
    return __uint_as_float(r);
}

// ---------------------------------------------------------------------------
// Projection GEMM (SIMT fp32): Q,K row-major; V written transposed and
// pre-rounded to tf32 (RNA) so the PV-phase MMA truncation is the identity.
// ---------------------------------------------------------------------------
__global__ __launch_bounds__(256) void proj_kernel(
    const float* __restrict__ X,
    const float* __restrict__ WQ,
    const float* __restrict__ WK,
    const float* __restrict__ WV)
{
    __shared__ float As[64][36];
    __shared__ float Bs[32][64];

    const int tid  = threadIdx.x;
    const int tx   = tid & 15;
    const int ty   = tid >> 4;
    const int row0 = blockIdx.x * 64;
    const int wsel = blockIdx.y >> 2;
    const int colB = (blockIdx.y & 3) * 64;

    const float* __restrict__ W = (wsel == 0) ? WQ : (wsel == 1) ? WK : WV;

    float acc[4][4] = {};

    for (int k0 = 0; k0 < DIM; k0 += 32) {
        #pragma unroll
        for (int it = 0; it < 2; ++it) {
            int s  = tid + it * 256;
            int r  = s >> 3;
            int k4 = (s & 7) * 4;
            float4 v = *reinterpret_cast<const float4*>(X + (row0 + r) * DIM + k0 + k4);
            *reinterpret_cast<float4*>(&As[r][k4]) = v;
        }
        #pragma unroll
        for (int it = 0; it < 2; ++it) {
            int s  = tid + it * 256;
            int kk = s >> 4;
            int c4 = (s & 15) * 4;
            float4 v = *reinterpret_cast<const float4*>(W + (k0 + kk) * DIM + colB + c4);
            *reinterpret_cast<float4*>(&Bs[kk][c4]) = v;
        }
        __syncthreads();

        #pragma unroll 8
        for (int kk = 0; kk < 32; ++kk) {
            float4 b = *reinterpret_cast<const float4*>(&Bs[kk][tx * 4]);
            float a0 = As[ty * 4 + 0][kk];
            float a1 = As[ty * 4 + 1][kk];
            float a2 = As[ty * 4 + 2][kk];
            float a3 = As[ty * 4 + 3][kk];
            acc[0][0] += a0 * b.x; acc[0][1] += a0 * b.y; acc[0][2] += a0 * b.z; acc[0][3] += a0 * b.w;
            acc[1][0] += a1 * b.x; acc[1][1] += a1 * b.y; acc[1][2] += a1 * b.z; acc[1][3] += a1 * b.w;
            acc[2][0] += a2 * b.x; acc[2][1] += a2 * b.y; acc[2][2] += a2 * b.z; acc[2][3] += a2 * b.w;
            acc[3][0] += a3 * b.x; acc[3][1] += a3 * b.y; acc[3][2] += a3 * b.z; acc[3][3] += a3 * b.w;
        }
        __syncthreads();
    }

    if (wsel == 2) {
        // transposed store, pre-rounded to tf32 RNA
        #pragma unroll
        for (int j = 0; j < 4; ++j) {
            float4 v = make_float4(tf32_rna(acc[0][j]), tf32_rna(acc[1][j]),
                                   tf32_rna(acc[2][j]), tf32_rna(acc[3][j]));
            *reinterpret_cast<float4*>(g_VT + (colB + tx * 4 + j) * NTOK + row0 + ty * 4) = v;
        }
    } else {
        float* O = (wsel == 0) ? g_Q : g_K;
        #pragma unroll
        for (int i = 0; i < 4; ++i) {
            float4 v = make_float4(acc[i][0], acc[i][1], acc[i][2], acc[i][3]);
            *reinterpret_cast<float4*>(O + (row0 + ty * 4 + i) * DIM + colB + tx * 4) = v;
        }
    }
}

// ---------------------------------------------------------------------------
// tf32 tensor-core flash attention (3xTF32 on S = QK^T, truncation-consistent)
// ---------------------------------------------------------------------------
__device__ __forceinline__ uint32_t smem_u32(const void* p) {
    return (uint32_t)__cvta_generic_to_shared(p);
}

#define LDSM_X4(R0, R1, R2, R3, ADDR)                                          \
    asm volatile("ldmatrix.sync.aligned.m8n8.x4.shared.b16 {%0,%1,%2,%3}, [%4];" \
                 : "=r"(R0), "=r"(R1), "=r"(R2), "=r"(R3) : "r"(ADDR))

__device__ __forceinline__ void mma_tf32(float c[4],
    uint32_t a0, uint32_t a1, uint32_t a2, uint32_t a3,
    uint32_t b0, uint32_t b1)
{
    asm volatile(
        "mma.sync.aligned.m16n8k8.row.col.f32.tf32.tf32.f32 "
        "{%0,%1,%2,%3},{%4,%5,%6,%7},{%8,%9},{%0,%1,%2,%3};"
        : "+f"(c[0]), "+f"(c[1]), "+f"(c[2]), "+f"(c[3])
        : "r"(a0), "r"(a1), "r"(a2), "r"(a3), "r"(b0), "r"(b1));
}

// residual after tf32 TRUNCATION (what the MMA hardware actually does to raw
// fp32 operands: it drops the low 13 mantissa bits). lo = x - trunc13(x).
__device__ __forceinline__ uint32_t tf32_lo(uint32_t xu) {
    float x  = __uint_as_float(xu);
    float hi = __uint_as_float(xu & 0xFFFFE000u);
    return __float_as_uint(x - hi);
}

__device__ __forceinline__ void cp16(void* dst_smem, const void* src_gmem) {
    uint32_t d = smem_u32(dst_smem);
    asm volatile("cp.async.cg.shared.global [%0], [%1], 16;" :: "r"(d), "l"(src_gmem));
}

extern __shared__ float fa_smem[];

__global__ __launch_bounds__(256, 1) void flash_kernel(float* __restrict__ out)
{
    float*  Qs  = fa_smem;                       // [64][260]
    float*  Ks  = Qs + 64 * LDQ;                 // 2 x [32][260]
    float*  VsT = Ks + 2 * 32 * LDK;             // 2 x [256][36]
    float*  Ps  = VsT + 2 * 256 * LDV;           // [64][36]
    float2* red = (float2*)(Ps + 64 * LDP);      // [2][64] (m, l) per column-half

    const int tid  = threadIdx.x;
    const int lane = tid & 31;
    const int wid  = tid >> 5;
    const int wr   = wid >> 1;       // row group: 16 q-rows
    const int wc   = wid & 1;        // column half
    const int g    = lane >> 2;      // group id
    const int t    = lane & 3;       // thread in group
    const int q0   = blockIdx.x * BM;

    // --- load Q tile (64x256) into smem, row-major, padded ---
    for (int s = tid; s < 64 * 64; s += 256) {
        int r = s >> 6, c = s & 63;
        float4 v = *reinterpret_cast<const float4*>(g_Q + (q0 + r) * DIM + c * 4);
        *reinterpret_cast<float4*>(Qs + r * LDQ + c * 4) = v;
    }

    // --- prefetch tile 0 (K + VT) via cp.async ---
    {
        const int k0 = 0;
        #pragma unroll
        for (int i = 0; i < 8; ++i) {
            int s = tid + i * 256;
            int r = s >> 6, c = s & 63;
            cp16(Ks + r * LDK + c * 4, g_K + (k0 + r) * DIM + c * 4);
        }
        #pragma unroll
        for (int i = 0; i < 8; ++i) {
            int s = tid + i * 256;
            int d = s >> 3, c = s & 7;
            cp16(VsT + d * LDV + c * 4, g_VT + d * NTOK + k0 + c * 4);
        }
        asm volatile("cp.async.commit_group;" ::: "memory");
    }

    // ldmatrix lane byte-offsets (fixed per thread)
    const uint32_t q_off = ((wr * 16 + (lane & 15)) * LDQ + ((lane >> 4) << 2)) * 4u;
    const uint32_t k_off = ((wc * 16 + ((lane >> 4) << 3) + (lane & 7)) * LDK
                            + (((lane >> 3) & 1) << 2)) * 4u;
    const uint32_t p_off = ((wr * 16 + (lane & 15)) * LDP + ((lane >> 4) << 2)) * 4u;
    const uint32_t v_off = ((wc * 128 + ((lane >> 4) << 3) + (lane & 7)) * LDV
                            + (((lane >> 3) & 1) << 2)) * 4u;

    const uint32_t qs_base = smem_u32(Qs) + q_off;
    const uint32_t ps_base = smem_u32(Ps) + p_off;

    float acc[16][4];
    #pragma unroll
    for (int i = 0; i < 16; ++i)
        #pragma unroll
        for (int j = 0; j < 4; ++j) acc[i][j] = 0.0f;

    float mrun0 = -1e30f, mrun1 = -1e30f;
    float lrun0 = 0.0f,   lrun1 = 0.0f;

    for (int tt = 0; tt < NT; ++tt) {
        const int buf = tt & 1;
        asm volatile("cp.async.wait_group 0;" ::: "memory");
        __syncthreads();                                 // tile tt data visible; prev compute done

        if (tt + 1 < NT) {                               // prefetch next tile into other buffer
            const int k0 = (tt + 1) * BK;
            float* kb = Ks  + ((tt + 1) & 1) * 32 * LDK;
            float* vb = VsT + ((tt + 1) & 1) * 256 * LDV;
            #pragma unroll
            for (int i = 0; i < 8; ++i) {
                int s = tid + i * 256;
                int r = s >> 6, c = s & 63;
                cp16(kb + r * LDK + c * 4, g_K + (k0 + r) * DIM + c * 4);
            }
            #pragma unroll
            for (int i = 0; i < 8; ++i) {
                int s = tid + i * 256;
                int d = s >> 3, c = s & 7;
                cp16(vb + d * LDV + c * 4, g_VT + d * NTOK + k0 + c * 4);
            }
            asm volatile("cp.async.commit_group;" ::: "memory");
        }

        // ---- S = Q K^T on this tile (3xTF32, truncation residuals) ----
        const uint32_t ks_base = smem_u32(Ks) + buf * 32 * LDK * 4 + k_off;
        float sacc[2][4];
        #pragma unroll
        for (int j = 0; j < 2; ++j) { sacc[j][0] = sacc[j][1] = sacc[j][2] = sacc[j][3] = 0.0f; }

        #pragma unroll
        for (int kk = 0; kk < 32; ++kk) {
            uint32_t a0, a1, a2, a3, b00, b01, b10, b11;
            LDSM_X4(a0, a1, a2, a3, qs_base + kk * 32u);
            LDSM_X4(b00, b01, b10, b11, ks_base + kk * 32u);
            // residuals vs the hardware's truncation of the raw operands
            uint32_t al0 = tf32_lo(a0), al1 = tf32_lo(a1), al2 = tf32_lo(a2), al3 = tf32_lo(a3);
            uint32_t bl00 = tf32_lo(b00), bl01 = tf32_lo(b01);
            uint32_t bl10 = tf32_lo(b10), bl11 = tf32_lo(b11);
            // hi*hi (hardware truncates raw operands = hi)
            mma_tf32(sacc[0], a0, a1, a2, a3, b00, b01);
            mma_tf32(sacc[1], a0, a1, a2, a3, b10, b11);
            // hi*lo
            mma_tf32(sacc[0], a0, a1, a2, a3, bl00, bl01);
            mma_tf32(sacc[1], a0, a1, a2, a3, bl10, bl11);
            // lo*hi
            mma_tf32(sacc[0], al0, al1, al2, al3, b00, b01);
            mma_tf32(sacc[1], al0, al1, al2, al3, b10, b11);
        }

        // ---- softmax (online, two column-halves merged through smem) ----
        float m0h = fmaxf(fmaxf(sacc[0][0], sacc[0][1]), fmaxf(sacc[1][0], sacc[1][1]));
        float m1h = fmaxf(fmaxf(sacc[0][2], sacc[0][3]), fmaxf(sacc[1][2], sacc[1][3]));
        #pragma unroll
        for (int o = 1; o <= 2; o <<= 1) {
            m0h = fmaxf(m0h, __shfl_xor_sync(0xffffffffu, m0h, o));
            m1h = fmaxf(m1h, __shfl_xor_sync(0xffffffffu, m1h, o));
        }
        sacc[0][0] = __expf(sacc[0][0] - m0h); sacc[0][1] = __expf(sacc[0][1] - m0h);
        sacc[1][0] = __expf(sacc[1][0] - m0h); sacc[1][1] = __expf(sacc[1][1] - m0h);
        sacc[0][2] = __expf(sacc[0][2] - m1h); sacc[0][3] = __expf(sacc[0][3] - m1h);
        sacc[1][2] = __expf(sacc[1][2] - m1h); sacc[1][3] = __expf(sacc[1][3] - m1h);
        float l0h = sacc[0][0] + sacc[0][1] + sacc[1][0] + sacc[1][1];
        float l1h = sacc[0][2] + sacc[0][3] + sacc[1][2] + sacc[1][3];
        #pragma unroll
        for (int o = 1; o <= 2; o <<= 1) {
            l0h += __shfl_xor_sync(0xffffffffu, l0h, o);
            l1h += __shfl_xor_sync(0xffffffffu, l1h, o);
        }
        if (t == 0) {
            red[wc * 64 + wr * 16 + g]     = make_float2(m0h, l0h);
            red[wc * 64 + wr * 16 + g + 8] = make_float2(m1h, l1h);
        }
        __syncthreads();

        // merge halves -> tile (m_t, l_t), then online update
        float2 fa0 = red[wr * 16 + g],        fb0 = red[64 + wr * 16 + g];
        float2 fa1 = red[wr * 16 + g + 8],    fb1 = red[64 + wr * 16 + g + 8];
        float mt0 = fmaxf(fa0.x, fb0.x);
        float lt0 = fa0.y * __expf(fa0.x - mt0) + fb0.y * __expf(fb0.x - mt0);
        float mt1 = fmaxf(fa1.x, fb1.x);
        float lt1 = fa1.y * __expf(fa1.x - mt1) + fb1.y * __expf(fb1.x - mt1);

        float mnew0 = fmaxf(mrun0, mt0);
        float sc0   = __expf(mrun0 - mnew0);
        lrun0 = lrun0 * sc0 + lt0 * __expf(mt0 - mnew0);
        float corr0 = __expf(m0h - mnew0);
        mrun0 = mnew0;

        float mnew1 = fmaxf(mrun1, mt1);
        float sc1   = __expf(mrun1 - mnew1);
        lrun1 = lrun1 * sc1 + lt1 * __expf(mt1 - mnew1);
        float corr1 = __expf(m1h - mnew1);
        mrun1 = mnew1;

        // rescale running O accumulators
        #pragma unroll
        for (int i = 0; i < 16; ++i) {
            acc[i][0] *= sc0; acc[i][1] *= sc0;
            acc[i][2] *= sc1; acc[i][3] *= sc1;
        }

        // store corrected P to smem, pre-rounded to tf32 RNA
        #pragma unroll
        for (int j = 0; j < 2; ++j) {
            int colb = wc * 16 + j * 8 + 2 * t;
            *reinterpret_cast<float2*>(Ps + (wr * 16 + g) * LDP + colb) =
                make_float2(tf32_rna(sacc[j][0] * corr0), tf32_rna(sacc[j][1] * corr0));
            *reinterpret_cast<float2*>(Ps + (wr * 16 + g + 8) * LDP + colb) =
                make_float2(tf32_rna(sacc[j][2] * corr1), tf32_rna(sacc[j][3] * corr1));
        }
        __syncthreads();

        // ---- O += P V : per-warp 16 rows x 128 cols, 16 n-tiles, 4 k-steps ----
        const uint32_t vs_base = smem_u32(VsT) + buf * 256 * LDV * 4 + v_off;
        #pragma unroll
        for (int ks = 0; ks < 4; ++ks) {
            uint32_t pa0, pa1, pa2, pa3;
            LDSM_X4(pa0, pa1, pa2, pa3, ps_base + ks * 32u);
            #pragma unroll
            for (int pr = 0; pr < 8; ++pr) {
                uint32_t b00, b01, b10, b11;
                LDSM_X4(b00, b01, b10, b11,
                        vs_base + (uint32_t)(pr * 16 * LDV * 4) + ks * 32u);
                mma_tf32(acc[pr * 2 + 0], pa0, pa1, pa2, pa3, b00, b01);
                mma_tf32(acc[pr * 2 + 1], pa0, pa1, pa2, pa3, b10, b11);
            }
        }
    }

    // ---- epilogue: normalize and store ----
    const float inv0 = 1.0f / lrun0;
    const float inv1 = 1.0f / lrun1;
    const int row0 = q0 + wr * 16 + g;
    #pragma unroll
    for (int i = 0; i < 16; ++i) {
        int col = wc * 128 + i * 8 + 2 * t;
        *reinterpret_cast<float2*>(out + row0 * DIM + col) =
            make_float2(acc[i][0] * inv0, acc[i][1] * inv0);
        *reinterpret_cast<float2*>(out + (row0 + 8) * DIM + col) =
            make_float2(acc[i][2] * inv1, acc[i][3] * inv1);
    }
}

// ---------------------------------------------------------------------------

static const int FA_SMEM_BYTES =
    (64 * LDQ + 2 * 32 * LDK + 2 * 256 * LDV + 64 * LDP) * (int)sizeof(float)
    + 128 * (int)sizeof(float2);   // 217088

extern "C" void kernel_launch(void* const* d_in, const int* in_sizes, int n_in,
                              void* d_out, int out_size)
{
    (void)in_sizes; (void)n_in; (void)out_size;
    const float* X  = (const float*)d_in[0];
    const float* WQ = (const float*)d_in[1];
    const float* WK = (const float*)d_in[2];
    const float* WV = (const float*)d_in[3];
    float* out = (float*)d_out;

    cudaFuncSetAttribute(flash_kernel, cudaFuncAttributeMaxDynamicSharedMemorySize, FA_SMEM_BYTES);

    proj_kernel<<<dim3(NTOK / 64, 12), 256>>>(X, WQ, WK, WV);
    flash_kernel<<<NTOK / BM, 256, FA_SMEM_BYTES>>>(out);
}

// round 8
// speedup vs baseline: 3.0962x; 1.3388x over previous
#include <cuda_runtime.h>
#include <cuda_bf16.h>
#include <cstdint>

#define NTOK 8192
#define DIM  256
#define BM   64
#define BK   32
#define NT   (NTOK / BK)     // 256 key tiles

#define LQB  264             // bf16 elements per smem row for Q/K (256 + 8 pad)
#define LDV  36              // floats (32 + 4 pad)
#define LDP  36

// smem byte offsets
#define SM_QH   0
#define SM_QL   (SM_QH + 64 * LQB * 2)        // 33792
#define SM_KH   (SM_QL + 64 * LQB * 2)        // 67584
#define SM_KL   (SM_KH + 2 * 32 * LQB * 2)    // 101376
#define SM_VT   (SM_KL + 2 * 32 * LQB * 2)    // 135168
#define SM_PS   (SM_VT + 2 * 256 * LDV * 4)   // 208896
#define SM_RED  (SM_PS + 64 * LDP * 4)        // 218112
#define SM_TOT  (SM_RED + 128 * 8)            // 219136
#define KBUF    (32 * LQB * 2)                // 16896 bytes per K buffer
#define VBUF    (256 * LDV * 4)               // 36864 bytes per V buffer

// Scratch: Q,K as bf16 hi/lo pairs; V tf32-rounded fp32, TRANSPOSED [dim][ntok].
__device__ __nv_bfloat16 g_Qh[NTOK * DIM];
__device__ __nv_bfloat16 g_Ql[NTOK * DIM];
__device__ __nv_bfloat16 g_Kh[NTOK * DIM];
__device__ __nv_bfloat16 g_Kl[NTOK * DIM];
__device__ float         g_VT[DIM * NTOK];

// round to tf32 (RNA); destination of cvt.rna.tf32.f32 is a .b32 register.
__device__ __forceinline__ float tf32_rna(float x) {
    uint32_t r;
    asm("cvt.rna.tf32.f32 %0, %1;" : "=r"(r) : "f"(x));
    return __uint_as_float(r);
}

// ---------------------------------------------------------------------------
// Projection GEMM (SIMT fp32). Q,K stored as bf16 hi/lo pairs; V stored
// transposed + tf32-RNA-rounded (so the PV MMA truncation is the identity).
// ---------------------------------------------------------------------------
__global__ __launch_bounds__(256) void proj_kernel(
    const float* __restrict__ X,
    const float* __restrict__ WQ,
    const float* __restrict__ WK,
    const float* __restrict__ WV)
{
    __shared__ float As[64][36];
    __shared__ float Bs[32][64];

    const int tid  = threadIdx.x;
    const int tx   = tid & 15;
    const int ty   = tid >> 4;
    const int row0 = blockIdx.x * 64;
    const int wsel = blockIdx.y >> 2;
    const int colB = (blockIdx.y & 3) * 64;

    const float* __restrict__ W = (wsel == 0) ? WQ : (wsel == 1) ? WK : WV;

    float acc[4][4] = {};

    for (int k0 = 0; k0 < DIM; k0 += 32) {
        #pragma unroll
        for (int it = 0; it < 2; ++it) {
            int s  = tid + it * 256;
            int r  = s >> 3;
            int k4 = (s & 7) * 4;
            float4 v = *reinterpret_cast<const float4*>(X + (row0 + r) * DIM + k0 + k4);
            *reinterpret_cast<float4*>(&As[r][k4]) = v;
        }
        #pragma unroll
        for (int it = 0; it < 2; ++it) {
            int s  = tid + it * 256;
            int kk = s >> 4;
            int c4 = (s & 15) * 4;
            float4 v = *reinterpret_cast<const float4*>(W + (k0 + kk) * DIM + colB + c4);
            *reinterpret_cast<float4*>(&Bs[kk][c4]) = v;
        }
        __syncthreads();

        #pragma unroll 8
        for (int kk = 0; kk < 32; ++kk) {
            float4 b = *reinterpret_cast<const float4*>(&Bs[kk][tx * 4]);
            float a0 = As[ty * 4 + 0][kk];
            float a1 = As[ty * 4 + 1][kk];
            float a2 = As[ty * 4 + 2][kk];
            float a3 = As[ty * 4 + 3][kk];
            acc[0][0] += a0 * b.x; acc[0][1] += a0 * b.y; acc[0][2] += a0 * b.z; acc[0][3] += a0 * b.w;
            acc[1][0] += a1 * b.x; acc[1][1] += a1 * b.y; acc[1][2] += a1 * b.z; acc[1][3] += a1 * b.w;
            acc[2][0] += a2 * b.x; acc[2][1] += a2 * b.y; acc[2][2] += a2 * b.z; acc[2][3] += a2 * b.w;
            acc[3][0] += a3 * b.x; acc[3][1] += a3 * b.y; acc[3][2] += a3 * b.z; acc[3][3] += a3 * b.w;
        }
        __syncthreads();
    }

    if (wsel == 2) {
        // transposed store, pre-rounded to tf32 RNA
        #pragma unroll
        for (int j = 0; j < 4; ++j) {
            float4 v = make_float4(tf32_rna(acc[0][j]), tf32_rna(acc[1][j]),
                                   tf32_rna(acc[2][j]), tf32_rna(acc[3][j]));
            *reinterpret_cast<float4*>(g_VT + (colB + tx * 4 + j) * NTOK + row0 + ty * 4) = v;
        }
    } else {
        __nv_bfloat16* Oh = (wsel == 0) ? g_Qh : g_Kh;
        __nv_bfloat16* Ol = (wsel == 0) ? g_Ql : g_Kl;
        #pragma unroll
        for (int i = 0; i < 4; ++i) {
            ushort4 hv, lv;
            unsigned short* hp = &hv.x;
            unsigned short* lp = &lv.x;
            #pragma unroll
            for (int j = 0; j < 4; ++j) {
                float x = acc[i][j];
                __nv_bfloat16 h = __float2bfloat16_rn(x);
                float r = x - __bfloat162float(h);
                __nv_bfloat16 l = __float2bfloat16_rn(r);
                hp[j] = __bfloat16_as_ushort(h);
                lp[j] = __bfloat16_as_ushort(l);
            }
            const int idx = (row0 + ty * 4 + i) * DIM + colB + tx * 4;
            *reinterpret_cast<ushort4*>(Oh + idx) = hv;
            *reinterpret_cast<ushort4*>(Ol + idx) = lv;
        }
    }
}

// ---------------------------------------------------------------------------
// Flash attention: bf16-pair (3-term) QK^T + tf32 PV.
// ---------------------------------------------------------------------------
__device__ __forceinline__ uint32_t smem_u32(const void* p) {
    return (uint32_t)__cvta_generic_to_shared(p);
}

#define LDSM_X4(R0, R1, R2, R3, ADDR)                                          \
    asm volatile("ldmatrix.sync.aligned.m8n8.x4.shared.b16 {%0,%1,%2,%3}, [%4];" \
                 : "=r"(R0), "=r"(R1), "=r"(R2), "=r"(R3) : "r"(ADDR))

__device__ __forceinline__ void mma_tf32(float c[4],
    uint32_t a0, uint32_t a1, uint32_t a2, uint32_t a3,
    uint32_t b0, uint32_t b1)
{
    asm volatile(
        "mma.sync.aligned.m16n8k8.row.col.f32.tf32.tf32.f32 "
        "{%0,%1,%2,%3},{%4,%5,%6,%7},{%8,%9},{%0,%1,%2,%3};"
        : "+f"(c[0]), "+f"(c[1]), "+f"(c[2]), "+f"(c[3])
        : "r"(a0), "r"(a1), "r"(a2), "r"(a3), "r"(b0), "r"(b1));
}

__device__ __forceinline__ void mma_bf16(float c[4],
    uint32_t a0, uint32_t a1, uint32_t a2, uint32_t a3,
    uint32_t b0, uint32_t b1)
{
    asm volatile(
        "mma.sync.aligned.m16n8k16.row.col.f32.bf16.bf16.f32 "
        "{%0,%1,%2,%3},{%4,%5,%6,%7},{%8,%9},{%0,%1,%2,%3};"
        : "+f"(c[0]), "+f"(c[1]), "+f"(c[2]), "+f"(c[3])
        : "r"(a0), "r"(a1), "r"(a2), "r"(a3), "r"(b0), "r"(b1));
}

__device__ __forceinline__ void cp16(uint32_t dst_smem, const void* src_gmem) {
    asm volatile("cp.async.cg.shared.global [%0], [%1], 16;" :: "r"(dst_smem), "l"(src_gmem));
}

extern __shared__ char fa_smem[];

__global__ __launch_bounds__(256, 1) void flash_kernel(float* __restrict__ out)
{
    const uint32_t sm = smem_u32(fa_smem);
    float*  Ps  = reinterpret_cast<float*>(fa_smem + SM_PS);
    float2* red = reinterpret_cast<float2*>(fa_smem + SM_RED);

    const int tid  = threadIdx.x;
    const int lane = tid & 31;
    const int wid  = tid >> 5;
    const int wr   = wid >> 1;       // row group: 16 q-rows
    const int wc   = wid & 1;        // column half (16 of 32 keys)
    const int g    = lane >> 2;      // group id
    const int t    = lane & 3;       // thread in group
    const int q0   = blockIdx.x * BM;

    // --- load Q hi/lo tiles (64x256 bf16 each) into padded smem rows ---
    for (int s = tid; s < 64 * 32; s += 256) {       // 16B chunks
        int r = s >> 5, c = s & 31;
        uint4 v = *reinterpret_cast<const uint4*>(g_Qh + (q0 + r) * DIM + c * 8);
        *reinterpret_cast<uint4*>(fa_smem + SM_QH + r * (LQB * 2) + c * 16) = v;
        uint4 w = *reinterpret_cast<const uint4*>(g_Ql + (q0 + r) * DIM + c * 8);
        *reinterpret_cast<uint4*>(fa_smem + SM_QL + r * (LQB * 2) + c * 16) = w;
    }

    // --- prefetch tile 0 (Kh, Kl, VT) via cp.async ---
    {
        #pragma unroll
        for (int i = 0; i < 4; ++i) {
            int s = tid + i * 256;                   // 1024 chunks of 16B
            int r = s >> 5, c = s & 31;
            cp16(sm + SM_KH + r * (LQB * 2) + c * 16, g_Kh + r * DIM + c * 8);
            cp16(sm + SM_KL + r * (LQB * 2) + c * 16, g_Kl + r * DIM + c * 8);
        }
        #pragma unroll
        for (int i = 0; i < 8; ++i) {
            int s = tid + i * 256;                   // 2048 chunks
            int d = s >> 3, c = s & 7;
            cp16(sm + SM_VT + d * (LDV * 4) + c * 16, g_VT + d * NTOK + c * 4);
        }
        asm volatile("cp.async.commit_group;" ::: "memory");
    }

    // ldmatrix lane byte-offsets
    const uint32_t qrow  = (uint32_t)(wr * 16 + (lane & 15));
    const uint32_t q_off = qrow * (LQB * 2) + ((lane >> 4) << 4);
    const uint32_t krow  = (uint32_t)(wc * 16 + ((lane >> 4) << 3) + (lane & 7));
    const uint32_t k_off = krow * (LQB * 2) + (((lane >> 3) & 1) << 4);
    const uint32_t p_off = ((wr * 16 + (lane & 15)) * LDP + ((lane >> 4) << 2)) * 4u;
    const uint32_t v_off = ((wc * 128 + ((lane >> 4) << 3) + (lane & 7)) * LDV
                            + (((lane >> 3) & 1) << 2)) * 4u;

    const uint32_t qh_base = sm + SM_QH + q_off;
    const uint32_t ql_base = sm + SM_QL + q_off;
    const uint32_t ps_base = sm + SM_PS + p_off;

    float acc[16][4];
    #pragma unroll
    for (int i = 0; i < 16; ++i)
        #pragma unroll
        for (int j = 0; j < 4; ++j) acc[i][j] = 0.0f;

    float mrun0 = -1e30f, mrun1 = -1e30f;
    float lrun0 = 0.0f,   lrun1 = 0.0f;

    for (int tt = 0; tt < NT; ++tt) {
        const int buf = tt & 1;
        asm volatile("cp.async.wait_group 0;" ::: "memory");
        __syncthreads();                             // tile tt visible; prev compute done

        if (tt + 1 < NT) {                           // prefetch next tile
            const int k0  = (tt + 1) * BK;
            const int nb  = (tt + 1) & 1;
            #pragma unroll
            for (int i = 0; i < 4; ++i) {
                int s = tid + i * 256;
                int r = s >> 5, c = s & 31;
                cp16(sm + SM_KH + nb * KBUF + r * (LQB * 2) + c * 16,
                     g_Kh + (k0 + r) * DIM + c * 8);
                cp16(sm + SM_KL + nb * KBUF + r * (LQB * 2) + c * 16,
                     g_Kl + (k0 + r) * DIM + c * 8);
            }
            #pragma unroll
            for (int i = 0; i < 8; ++i) {
                int s = tid + i * 256;
                int d = s >> 3, c = s & 7;
                cp16(sm + SM_VT + nb * VBUF + d * (LDV * 4) + c * 16,
                     g_VT + d * NTOK + k0 + c * 4);
            }
            asm volatile("cp.async.commit_group;" ::: "memory");
        }

        // ---- S = Q K^T (bf16-pair, 3 terms): 16 k16-steps ----
        const uint32_t kh_base = sm + SM_KH + buf * KBUF + k_off;
        const uint32_t kl_base = sm + SM_KL + buf * KBUF + k_off;
        float sacc[2][4];
        #pragma unroll
        for (int j = 0; j < 2; ++j) { sacc[j][0] = sacc[j][1] = sacc[j][2] = sacc[j][3] = 0.0f; }

        #pragma unroll
        for (int kk = 0; kk < 16; ++kk) {
            uint32_t ah0, ah1, ah2, ah3, al0, al1, al2, al3;
            uint32_t bh0, bh1, bh2, bh3, bl0, bl1, bl2, bl3;
            LDSM_X4(ah0, ah1, ah2, ah3, qh_base + kk * 32u);
            LDSM_X4(al0, al1, al2, al3, ql_base + kk * 32u);
            LDSM_X4(bh0, bh1, bh2, bh3, kh_base + kk * 32u);
            LDSM_X4(bl0, bl1, bl2, bl3, kl_base + kk * 32u);
            // hi*hi
            mma_bf16(sacc[0], ah0, ah1, ah2, ah3, bh0, bh1);
            mma_bf16(sacc[1], ah0, ah1, ah2, ah3, bh2, bh3);
            // hi*lo
            mma_bf16(sacc[0], ah0, ah1, ah2, ah3, bl0, bl1);
            mma_bf16(sacc[1], ah0, ah1, ah2, ah3, bl2, bl3);
            // lo*hi
            mma_bf16(sacc[0], al0, al1, al2, al3, bh0, bh1);
            mma_bf16(sacc[1], al0, al1, al2, al3, bh2, bh3);
        }

        // ---- softmax (online, two column-halves merged through smem) ----
        float m0h = fmaxf(fmaxf(sacc[0][0], sacc[0][1]), fmaxf(sacc[1][0], sacc[1][1]));
        float m1h = fmaxf(fmaxf(sacc[0][2], sacc[0][3]), fmaxf(sacc[1][2], sacc[1][3]));
        #pragma unroll
        for (int o = 1; o <= 2; o <<= 1) {
            m0h = fmaxf(m0h, __shfl_xor_sync(0xffffffffu, m0h, o));
            m1h = fmaxf(m1h, __shfl_xor_sync(0xffffffffu, m1h, o));
        }
        sacc[0][0] = __expf(sacc[0][0] - m0h); sacc[0][1] = __expf(sacc[0][1] - m0h);
        sacc[1][0] = __expf(sacc[1][0] - m0h); sacc[1][1] = __expf(sacc[1][1] - m0h);
        sacc[0][2] = __expf(sacc[0][2] - m1h); sacc[0][3] = __expf(sacc[0][3] - m1h);
        sacc[1][2] = __expf(sacc[1][2] - m1h); sacc[1][3] = __expf(sacc[1][3] - m1h);
        float l0h = sacc[0][0] + sacc[0][1] + sacc[1][0] + sacc[1][1];
        float l1h = sacc[0][2] + sacc[0][3] + sacc[1][2] + sacc[1][3];
        #pragma unroll
        for (int o = 1; o <= 2; o <<= 1) {
            l0h += __shfl_xor_sync(0xffffffffu, l0h, o);
            l1h += __shfl_xor_sync(0xffffffffu, l1h, o);
        }
        if (t == 0) {
            red[wc * 64 + wr * 16 + g]     = make_float2(m0h, l0h);
            red[wc * 64 + wr * 16 + g + 8] = make_float2(m1h, l1h);
        }
        __syncthreads();

        // merge halves -> tile (m_t, l_t), then online update
        float2 fa0 = red[wr * 16 + g],        fb0 = red[64 + wr * 16 + g];
        float2 fa1 = red[wr * 16 + g + 8],    fb1 = red[64 + wr * 16 + g + 8];
        float mt0 = fmaxf(fa0.x, fb0.x);
        float lt0 = fa0.y * __expf(fa0.x - mt0) + fb0.y * __expf(fb0.x - mt0);
        float mt1 = fmaxf(fa1.x, fb1.x);
        float lt1 = fa1.y * __expf(fa1.x - mt1) + fb1.y * __expf(fb1.x - mt1);

        float mnew0 = fmaxf(mrun0, mt0);
        float sc0   = __expf(mrun0 - mnew0);
        lrun0 = lrun0 * sc0 + lt0 * __expf(mt0 - mnew0);
        float corr0 = __expf(m0h - mnew0);
        mrun0 = mnew0;

        float mnew1 = fmaxf(mrun1, mt1);
        float sc1   = __expf(mrun1 - mnew1);
        lrun1 = lrun1 * sc1 + lt1 * __expf(mt1 - mnew1);
        float corr1 = __expf(m1h - mnew1);
        mrun1 = mnew1;

        // rescale running O accumulators
        #pragma unroll
        for (int i = 0; i < 16; ++i) {
            acc[i][0] *= sc0; acc[i][1] *= sc0;
            acc[i][2] *= sc1; acc[i][3] *= sc1;
        }

        // store corrected P to smem, pre-rounded to tf32 RNA
        #pragma unroll
        for (int j = 0; j < 2; ++j) {
            int colb = wc * 16 + j * 8 + 2 * t;
            *reinterpret_cast<float2*>(Ps + (wr * 16 + g) * LDP + colb) =
                make_float2(tf32_rna(sacc[j][0] * corr0), tf32_rna(sacc[j][1] * corr0));
            *reinterpret_cast<float2*>(Ps + (wr * 16 + g + 8) * LDP + colb) =
                make_float2(tf32_rna(sacc[j][2] * corr1), tf32_rna(sacc[j][3] * corr1));
        }
        __syncthreads();

        // ---- O += P V : tf32, 16 n-tiles x 4 k8-steps ----
        const uint32_t vs_base = sm + SM_VT + buf * VBUF + v_off;
        #pragma unroll
        for (int ks = 0; ks < 4; ++ks) {
            uint32_t pa0, pa1, pa2, pa3;
            LDSM_X4(pa0, pa1, pa2, pa3, ps_base + ks * 32u);
            #pragma unroll
            for (int pr = 0; pr < 8; ++pr) {
                uint32_t b00, b01, b10, b11;
                LDSM_X4(b00, b01, b10, b11,
                        vs_base + (uint32_t)(pr * 16 * LDV * 4) + ks * 32u);
                mma_tf32(acc[pr * 2 + 0], pa0, pa1, pa2, pa3, b00, b01);
                mma_tf32(acc[pr * 2 + 1], pa0, pa1, pa2, pa3, b10, b11);
            }
        }
    }

    // ---- epilogue: normalize and store ----
    const float inv0 = 1.0f / lrun0;
    const float inv1 = 1.0f / lrun1;
    const int row0 = q0 + wr * 16 + g;
    #pragma unroll
    for (int i = 0; i < 16; ++i) {
        int col = wc * 128 + i * 8 + 2 * t;
        *reinterpret_cast<float2*>(out + row0 * DIM + col) =
            make_float2(acc[i][0] * inv0, acc[i][1] * inv0);
        *reinterpret_cast<float2*>(out + (row0 + 8) * DIM + col) =
            make_float2(acc[i][2] * inv1, acc[i][3] * inv1);
    }
}

// ---------------------------------------------------------------------------

extern "C" void kernel_launch(void* const* d_in, const int* in_sizes, int n_in,
                              void* d_out, int out_size)
{
    (void)in_sizes; (void)n_in; (void)out_size;
    const float* X  = (const float*)d_in[0];
    const float* WQ = (const float*)d_in[1];
    const float* WK = (const float*)d_in[2];
    const float* WV = (const float*)d_in[3];
    float* out = (float*)d_out;

    cudaFuncSetAttribute(flash_kernel, cudaFuncAttributeMaxDynamicSharedMemorySize, SM_TOT);

    proj_kernel<<<dim3(NTOK / 64, 12), 256>>>(X, WQ, WK, WV);
    flash_kernel<<<NTOK / BM, 256, SM_TOT>>>(out);
}